// round 12
// baseline (speedup 1.0000x reference)
#include <cuda_runtime.h>
#include <cstdint>
#include <cstddef>

#define B_ 256
#define T_ 2048
#define I_ 128
#define H_ 64
#define G_ 256          // 4*H
#define M_ (B_*T_)      // 524288

// Scratch (device globals: allocation-free rule)
__device__ float g_pre[(size_t)M_ * G_];   // 512 MB
__device__ float g_h0 [(size_t)M_ * H_];   // 128 MB
__device__ float g_h1 [(size_t)M_ * H_];   // 128 MB

// ---------------------------------------------------------------- helpers
__device__ __forceinline__ void mma_tf32(float c[4], const unsigned a[4],
                                         unsigned b0, unsigned b1){
    asm volatile("mma.sync.aligned.m16n8k8.row.col.f32.tf32.tf32.f32 "
        "{%0,%1,%2,%3},{%4,%5,%6,%7},{%8,%9},{%0,%1,%2,%3};"
        : "+f"(c[0]),"+f"(c[1]),"+f"(c[2]),"+f"(c[3])
        : "r"(a[0]),"r"(a[1]),"r"(a[2]),"r"(a[3]),"r"(b0),"r"(b1));
}

__device__ __forceinline__ float tanh_fast(float x){
    float y; asm("tanh.approx.f32 %0, %1;" : "=f"(y) : "f"(x)); return y;
}

__device__ __forceinline__ unsigned smaddr(const void* p){
    return (unsigned)__cvta_generic_to_shared(p);
}
__device__ __forceinline__ void cp16(unsigned dst, const void* src){
    asm volatile("cp.async.cg.shared.global [%0], [%1], 16;" :: "r"(dst), "l"(src));
}

// ---------------------------------------------------------------- pre-GEMM
// (R8 exact) 512 threads, BM=128, N=256, K chunked 32, cp.async dbl buffer.
#define KC 32
#define KP 36
#define STAGE_F (128*KP + 256*KP)

template<int K>
__global__ void __launch_bounds__(512,1)
gemm_pre(const float* __restrict__ A, const float* __restrict__ W,
         const float* __restrict__ b_ih, const float* __restrict__ b_hh,
         float* __restrict__ out)
{
    extern __shared__ float sm[];
    float* bs = sm + 2*STAGE_F;

    const int tid = threadIdx.x;
    const size_t m0 = (size_t)blockIdx.x * 128;

    if (tid < 256) bs[tid] = b_ih[tid] + b_hh[tid];

    auto copy_chunk = [&](int c, int st){
        float* Asd = sm + st*STAGE_F;
        float* Wsd = Asd + 128*KP;
        #pragma unroll
        for (int i = tid; i < 128*8; i += 512){
            int row = i >> 3, seg = i & 7;
            cp16(smaddr(Asd + row*KP + seg*4),
                 A + (m0 + row)*(size_t)K + c*KC + seg*4);
        }
        #pragma unroll
        for (int i = tid; i < 256*8; i += 512){
            int row = i >> 3, seg = i & 7;
            cp16(smaddr(Wsd + row*KP + seg*4),
                 W + (size_t)row*K + c*KC + seg*4);
        }
    };

    const int warp = tid >> 5, lane = tid & 31;
    const int wm = warp >> 2, wn = warp & 3;
    const int gid = lane >> 2, tig = lane & 3;

    float acc[2][8][4];
    #pragma unroll
    for (int a = 0; a < 2; a++)
        #pragma unroll
        for (int b = 0; b < 8; b++)
            #pragma unroll
            for (int d = 0; d < 4; d++) acc[a][b][d] = 0.f;

    constexpr int NCH = K / KC;

    copy_chunk(0, 0);
    asm volatile("cp.async.commit_group;");

    for (int c = 0; c < NCH; ++c){
        if (c + 1 < NCH){
            copy_chunk(c + 1, (c + 1) & 1);
            asm volatile("cp.async.commit_group;");
            asm volatile("cp.async.wait_group 1;");
        } else {
            asm volatile("cp.async.wait_group 0;");
        }
        __syncthreads();

        const float* As = sm + (c & 1)*STAGE_F;
        const float* Ws = As + 128*KP;

        #pragma unroll
        for (int ks = 0; ks < KC/8; ++ks){
            const int cc = ks*8 + tig;
            unsigned af[2][4];
            #pragma unroll
            for (int mt = 0; mt < 2; mt++){
                int r = wm*32 + mt*16 + gid;
                af[mt][0] = __float_as_uint(As[r*KP + cc]);
                af[mt][1] = __float_as_uint(As[(r+8)*KP + cc]);
                af[mt][2] = __float_as_uint(As[r*KP + cc + 4]);
                af[mt][3] = __float_as_uint(As[(r+8)*KP + cc + 4]);
            }
            #pragma unroll
            for (int nt = 0; nt < 8; nt++){
                int n = wn*64 + nt*8 + gid;
                unsigned b0 = __float_as_uint(Ws[n*KP + cc]);
                unsigned b1 = __float_as_uint(Ws[n*KP + cc + 4]);
                mma_tf32(acc[0][nt], af[0], b0, b1);
                mma_tf32(acc[1][nt], af[1], b0, b1);
            }
        }
        __syncthreads();
    }

    #pragma unroll
    for (int mt = 0; mt < 2; mt++){
        size_t r = m0 + wm*32 + mt*16 + gid;
        #pragma unroll
        for (int nt = 0; nt < 8; nt++){
            int col = wn*64 + nt*8 + 2*tig;
            float bb0 = bs[col], bb1 = bs[col+1];
            *(float2*)(out + r*G_ + col)
                = make_float2(acc[mt][nt][0] + bb0, acc[mt][nt][1] + bb1);
            *(float2*)(out + (r+8)*G_ + col)
                = make_float2(acc[mt][nt][2] + bb0, acc[mt][nt][3] + bb1);
        }
    }
}

// ---------------------------------------------------------------- LSTM scan
// TENSOR-CORE scan. Block = 8 sequences, 256 threads (8 warps), grid 32.
// Per step: gates[8,256] = h[8,64] @ W_hh^T on mma.m16n8k8.tf32 (A = h from
// smem, rows 8-15 zero; B = weights preloaded in 64 regs/lane; C rows 0-7
// used). Warp w owns gates [w*32, w*32+32) -> activation type = w>>1 is
// WARP-UNIFORM. pre staged by cp.async double buffer. Activated gates go
// through smem; cell update by 256 threads (2 cells each, c in registers).
// 2 barriers/step. h double-buffered in smem.
#define SQ 8                      // sequences per block
#define PRP 264                   // padded row (floats) for pre/act
#define HRP 68                    // padded row for h

__global__ void __launch_bounds__(256,1)
lstm_scan(const float* __restrict__ pre, const float* __restrict__ w_hh,
          float* __restrict__ h_out)
{
    __shared__ __align__(16) float pre_s[2][SQ][PRP];
    __shared__ __align__(16) float act_s[SQ][PRP];
    __shared__ __align__(16) float h_s[2][SQ][HRP];

    const int tid  = threadIdx.x;
    const int warp = tid >> 5, lane = tid & 31;
    const int gid  = lane >> 2, tig = lane & 3;
    const int sbase = blockIdx.x * SQ;

    // zero h buffers
    for (int i = tid; i < 2*SQ*HRP; i += 256) ((float*)h_s)[i] = 0.f;

    // preload B-fragments: warp w covers gates w*32+nsub*8+gid, all K
    unsigned bw[4][8][2];
    {
        const float* wbase = w_hh;
        #pragma unroll
        for (int nsub = 0; nsub < 4; nsub++){
            int gate = warp*32 + nsub*8 + gid;
            #pragma unroll
            for (int ks = 0; ks < 8; ks++){
                bw[nsub][ks][0] = __float_as_uint(wbase[gate*H_ + ks*8 + tig]);
                bw[nsub][ks][1] = __float_as_uint(wbase[gate*H_ + ks*8 + tig + 4]);
            }
        }
    }

    // warp-uniform activation constants (gate type = warp>>1; 2 => tanh)
    const int   tau = warp >> 1;
    const float am  = (tau == 2) ? 1.f : 0.5f;   // arg scale & output scale
    const float ab  = (tau == 2) ? 0.f : 0.5f;

    // cp.async staging of pre: per step 8 seq x 256 floats; 2 cp16/thread
    auto stage_pre = [&](int t, int buf){
        #pragma unroll
        for (int r = 0; r < 2; r++){
            int idx = tid + r*256;            // 0..511
            int seq = idx >> 6, seg = idx & 63;
            cp16(smaddr(&pre_s[buf][seq][seg*4]),
                 pre + ((size_t)(sbase + seq)*T_ + t)*G_ + seg*4);
        }
    };

    stage_pre(0, 0);
    asm volatile("cp.async.commit_group;");
    stage_pre(1, 1);
    asm volatile("cp.async.commit_group;");
    asm volatile("cp.async.wait_group 1;");   // pre[0] ready
    __syncthreads();

    // cell state: thread u -> seq s = u>>5, cells 2q, 2q+1 (q = u&31)
    const int cs = tid >> 5, cq = tid & 31;
    float c0 = 0.f, c1 = 0.f;

    for (int t = 0; t < T_; ++t){
        const int rb = t & 1;

        // ---- gates = h @ W^T on tensor cores (C rows 0-7 = seqs)
        float C[4][4];
        #pragma unroll
        for (int n = 0; n < 4; n++){
            C[n][0] = 0.f; C[n][1] = 0.f; C[n][2] = 0.f; C[n][3] = 0.f;
        }
        #pragma unroll
        for (int ks = 0; ks < 8; ks++){
            unsigned a[4];
            a[0] = __float_as_uint(h_s[rb][gid][ks*8 + tig]);
            a[1] = 0u;
            a[2] = __float_as_uint(h_s[rb][gid][ks*8 + tig + 4]);
            a[3] = 0u;
            #pragma unroll
            for (int nsub = 0; nsub < 4; nsub++)
                mma_tf32(C[nsub], a, bw[nsub][ks][0], bw[nsub][ks][1]);
        }

        // ---- add pre, activate, store to act_s (c0/c1 = seq gid, gates g0+2tig, +1)
        #pragma unroll
        for (int nsub = 0; nsub < 4; nsub++){
            int g = warp*32 + nsub*8 + 2*tig;
            float2 p = *(const float2*)&pre_s[rb][gid][g];
            float v0 = fmaf(tanh_fast((C[nsub][0] + p.x) * am), am, ab);
            float v1 = fmaf(tanh_fast((C[nsub][1] + p.y) * am), am, ab);
            *(float2*)&act_s[gid][g] = make_float2(v0, v1);
        }
        __syncthreads();                       // BAR1: acts ready, pre[t] consumed

        // refill pre buffer for t+2 (overwrites buf rb, now free)
        {
            int tc = (t + 2 < T_) ? t + 2 : T_ - 1;
            stage_pre(tc, rb);
            asm volatile("cp.async.commit_group;");
        }

        // ---- cell update: 2 cells per thread
        {
            float2 iv = *(const float2*)&act_s[cs][      2*cq];
            float2 fv = *(const float2*)&act_s[cs][ 64 + 2*cq];
            float2 gv = *(const float2*)&act_s[cs][128 + 2*cq];
            float2 ov = *(const float2*)&act_s[cs][192 + 2*cq];
            c0 = fmaf(fv.x, c0, iv.x * gv.x);
            c1 = fmaf(fv.y, c1, iv.y * gv.y);
            float h0v = ov.x * tanh_fast(c0);
            float h1v = ov.y * tanh_fast(c1);
            *(float2*)&h_s[rb ^ 1][cs][2*cq] = make_float2(h0v, h1v);
            *(float2*)(h_out + ((size_t)(sbase + cs)*T_ + t)*H_ + 2*cq)
                = make_float2(h0v, h1v);
        }

        asm volatile("cp.async.wait_group 1;");   // pre[t+1] ready
        __syncthreads();                          // BAR2: h(t+1), pre(t+1) published
    }
}

// ---------------------------------------------------------------- FC head
__global__ void fc_kernel(const float* __restrict__ h, const float* __restrict__ fw,
                          const float* __restrict__ fb, float* __restrict__ out)
{
    size_t m = (size_t)blockIdx.x * blockDim.x + threadIdx.x;
    const float4* hv = (const float4*)(h + m * H_);
    float acc = 0.f;
    #pragma unroll
    for (int i = 0; i < H_/4; i++){
        float4 a = hv[i];
        float4 w = __ldg(((const float4*)fw) + i);
        acc = fmaf(a.x, w.x, fmaf(a.y, w.y, fmaf(a.z, w.z, fmaf(a.w, w.w, acc))));
    }
    out[m] = acc + __ldg(fb);
}

// ---------------------------------------------------------------- launch
extern "C" void kernel_launch(void* const* d_in, const int* in_sizes, int n_in,
                              void* d_out, int out_size)
{
    const float* x     = (const float*)d_in[0];
    const float* w_ih0 = (const float*)d_in[1];
    const float* w_hh0 = (const float*)d_in[2];
    const float* b_ih0 = (const float*)d_in[3];
    const float* b_hh0 = (const float*)d_in[4];
    const float* w_ih1 = (const float*)d_in[5];
    const float* w_hh1 = (const float*)d_in[6];
    const float* b_ih1 = (const float*)d_in[7];
    const float* b_hh1 = (const float*)d_in[8];
    const float* w_ih2 = (const float*)d_in[9];
    const float* w_hh2 = (const float*)d_in[10];
    const float* b_ih2 = (const float*)d_in[11];
    const float* b_hh2 = (const float*)d_in[12];
    const float* fc_w  = (const float*)d_in[13];
    const float* fc_b  = (const float*)d_in[14];
    float* out = (float*)d_out;

    float *pre, *h0, *h1;
    cudaGetSymbolAddress((void**)&pre, g_pre);
    cudaGetSymbolAddress((void**)&h0,  g_h0);
    cudaGetSymbolAddress((void**)&h1,  g_h1);

    const int smemG = (2*STAGE_F + 256) * 4;
    cudaFuncSetAttribute(gemm_pre<128>, cudaFuncAttributeMaxDynamicSharedMemorySize, smemG);
    cudaFuncSetAttribute(gemm_pre<64>,  cudaFuncAttributeMaxDynamicSharedMemorySize, smemG);

    gemm_pre<128><<<M_/128, 512, smemG>>>(x,  w_ih0, b_ih0, b_hh0, pre);
    lstm_scan    <<<B_/SQ,  256>>>(pre, w_hh0, h0);
    gemm_pre<64> <<<M_/128, 512, smemG>>>(h0, w_ih1, b_ih1, b_hh1, pre);
    lstm_scan    <<<B_/SQ,  256>>>(pre, w_hh1, h1);
    gemm_pre<64> <<<M_/128, 512, smemG>>>(h1, w_ih2, b_ih2, b_hh2, pre);
    lstm_scan    <<<B_/SQ,  256>>>(pre, w_hh2, h0);
    fc_kernel    <<<M_/256, 256>>>(h0, fc_w, fc_b, out);
}